// round 2
// baseline (speedup 1.0000x reference)
#include <cuda_runtime.h>
#include <math.h>

#define NB 8
#define NTOK 1024
#define CH 768
#define CH2 1536
#define CH4 3072
#define RPT 8192            // rows per tensor (B*N)
#define ROWS 49152          // 6 tensors * RPT

// ---------------- scratch (static device allocations; no cudaMalloc) ----------------
__device__ float g_ln[(size_t)ROWS * CH];      // layernorm outputs (reused for LN2)
__device__ float g_proj[(size_t)ROWS * CH2];   // proj output: qk = cols [0,768), v = cols [768,1536)
__device__ float g_xo[(size_t)ROWS * CH];      // attention-combined outputs (residual source)
__device__ float g_h[(size_t)ROWS * CH4];      // fc1 activations
__device__ float g_D[(size_t)NB * NTOK * NTOK];// one batched distance matrix (reused 27x)
__device__ float g_qk2[ROWS];                  // per-row squared norms of qk
__device__ float g_stats[54];                  // 27 x {min, max}
__device__ float g_vec[10 * RPT];              // S_a, S_p1, d11a..d22a, d11p..d22p
__device__ float g_scr[2 * RPT];               // invr, invc scratch
__device__ float g_maps[6 * RPT];              // per-tensor attention maps (t-ordered)

// ---------------- helpers ----------------
__device__ __forceinline__ float2 blockReduce2(float a, float b) {
    __shared__ float sa[8], sb[8];
    __shared__ float2 res;
    int lane = threadIdx.x & 31;
    int w = threadIdx.x >> 5;
#pragma unroll
    for (int o = 16; o > 0; o >>= 1) {
        a += __shfl_down_sync(0xffffffffu, a, o);
        b += __shfl_down_sync(0xffffffffu, b, o);
    }
    if (lane == 0) { sa[w] = a; sb[w] = b; }
    __syncthreads();
    if (threadIdx.x == 0) {
        float ta = 0.f, tb = 0.f;
#pragma unroll
        for (int i = 0; i < 8; i++) { ta += sa[i]; tb += sb[i]; }
        res.x = ta; res.y = tb;
    }
    __syncthreads();
    return res;
}

__device__ __forceinline__ float gelu_exact(float x) {
    return 0.5f * x * (1.0f + erff(x * 0.70710678118654752f));
}

// ---------------- small kernels ----------------
__global__ void init_stats_kernel() {
    int i = threadIdx.x;
    if (i < 27) {
        g_stats[2 * i]     = __int_as_float(0x7f800000);  // +inf
        g_stats[2 * i + 1] = 0.f;                          // distances >= 0
    }
}

__device__ __forceinline__ void ln_body(const float* __restrict__ src,
                                        const float* __restrict__ w,
                                        const float* __restrict__ bb,
                                        float* __restrict__ dst) {
    int c = threadIdx.x;
    float v0 = src[c], v1 = src[c + 256], v2 = src[c + 512];
    float s  = v0 + v1 + v2;
    float s2 = v0 * v0 + v1 * v1 + v2 * v2;
    float2 r = blockReduce2(s, s2);
    float mu  = r.x * (1.0f / CH);
    float var = r.y * (1.0f / CH) - mu * mu;
    float inv = rsqrtf(var + 1e-5f);
    dst[c]       = (v0 - mu) * inv * w[c]       + bb[c];
    dst[c + 256] = (v1 - mu) * inv * w[c + 256] + bb[c + 256];
    dst[c + 512] = (v2 - mu) * inv * w[c + 512] + bb[c + 512];
}

__global__ void ln_gather_kernel(const float* __restrict__ anc, const float* __restrict__ pos,
                                 const float* __restrict__ n1, const float* __restrict__ n2,
                                 const float* __restrict__ w, const float* __restrict__ bb) {
    int row = blockIdx.x;
    int t = row / RPT;
    int q = row - t * RPT;
    const float* src;
    switch (t) {
        case 0: src = anc + (size_t)q * CH; break;
        case 1: src = pos + (size_t)q * CH; break;
        case 2: src = n1 + (size_t)q * CH; break;
        case 3: src = n1 + ((size_t)RPT + q) * CH; break;
        case 4: src = n2 + (size_t)q * CH; break;
        default: src = n2 + ((size_t)RPT + q) * CH; break;
    }
    ln_body(src, w, bb, g_ln + (size_t)row * CH);
}

__global__ void ln_plain_kernel(const float* __restrict__ x,
                                const float* __restrict__ w, const float* __restrict__ bb) {
    int row = blockIdx.x;
    ln_body(x + (size_t)row * CH, w, bb, g_ln + (size_t)row * CH);
}

__global__ void qksq_kernel() {
    int row = blockIdx.x;
    const float* p = g_proj + (size_t)row * CH2;   // qk = first 768 cols
    int c = threadIdx.x;
    float v0 = p[c], v1 = p[c + 256], v2 = p[c + 512];
    float2 r = blockReduce2(v0 * v0 + v1 * v1 + v2 * v2, 0.f);
    if (threadIdx.x == 0) g_qk2[row] = r.x;
}

// ---------------- GEMM NN: C[M,N] = A[M,K] @ B[K,N] (+bias, epilogue) ----------------
// grid: (N/128, M/128), 256 threads. mode: 0=bias, 1=bias+gelu, 2=bias+residual
__global__ void __launch_bounds__(256) gemm_nn_kernel(
        const float* __restrict__ A, int lda,
        const float* __restrict__ Bm, int ldb,
        float* __restrict__ Cm, int ldc, int K,
        const float* __restrict__ bias, int mode,
        const float* __restrict__ resid, int ldr) {
    __shared__ float As[8][128];
    __shared__ float Bs[8][128];
    const int tid = threadIdx.x;
    const int m0 = blockIdx.y * 128;
    const int n0 = blockIdx.x * 128;
    const int arow = tid >> 1, acol = (tid & 1) * 4;
    const int brow = tid >> 5, bcol = (tid & 31) * 4;
    const float* Ap = A + (size_t)(m0 + arow) * lda + acol;
    const float* Bp = Bm + (size_t)brow * ldb + n0 + bcol;
    const int tx = tid & 15, ty = tid >> 4;
    float acc[8][8] = {};
    for (int k0 = 0; k0 < K; k0 += 8) {
        float4 a4 = *(const float4*)(Ap + k0);
        float4 b4 = *(const float4*)(Bp + (size_t)k0 * ldb);
        As[acol + 0][arow] = a4.x; As[acol + 1][arow] = a4.y;
        As[acol + 2][arow] = a4.z; As[acol + 3][arow] = a4.w;
        *(float4*)(&Bs[brow][bcol]) = b4;
        __syncthreads();
#pragma unroll
        for (int k = 0; k < 8; k++) {
            float ar[8], br[8];
#pragma unroll
            for (int i = 0; i < 8; i++) ar[i] = As[k][ty * 8 + i];
#pragma unroll
            for (int j = 0; j < 8; j++) br[j] = Bs[k][tx * 8 + j];
#pragma unroll
            for (int i = 0; i < 8; i++)
#pragma unroll
                for (int j = 0; j < 8; j++)
                    acc[i][j] = fmaf(ar[i], br[j], acc[i][j]);
        }
        __syncthreads();
    }
#pragma unroll
    for (int i = 0; i < 8; i++) {
        int m = m0 + ty * 8 + i;
#pragma unroll
        for (int j = 0; j < 8; j++) {
            int n = n0 + tx * 8 + j;
            float v = acc[i][j] + bias[n];
            if (mode == 1) v = gelu_exact(v);
            else if (mode == 2) v += resid[(size_t)m * ldr + n];
            Cm[(size_t)m * ldc + n] = v;
        }
    }
}

// ---------------- cdist (NT): D[b,i,j] = ||X[b,i]-Y[b,j]||, fused global min/max ----------------
// grid: (8 jtiles, 8 itiles, NB), 256 threads. X,Y are qk slices (ld = CH2).
__global__ void __launch_bounds__(256) cdist_kernel(
        const float* __restrict__ X, const float* __restrict__ x2,
        const float* __restrict__ Y, const float* __restrict__ y2,
        float* __restrict__ stats) {
    __shared__ float As[8][128];
    __shared__ float Bs[8][128];
    const int tid = threadIdx.x;
    const int b = blockIdx.z;
    const int i0 = blockIdx.y * 128;
    const int j0 = blockIdx.x * 128;
    const int arow = tid >> 1, acol = (tid & 1) * 4;
    const float* Xp = X + (size_t)(b * NTOK + i0 + arow) * CH2 + acol;
    const float* Yp = Y + (size_t)(b * NTOK + j0 + arow) * CH2 + acol;
    const int tx = tid & 15, ty = tid >> 4;
    float acc[8][8] = {};
    for (int k0 = 0; k0 < CH; k0 += 8) {
        float4 a4 = *(const float4*)(Xp + k0);
        float4 b4 = *(const float4*)(Yp + k0);
        As[acol + 0][arow] = a4.x; As[acol + 1][arow] = a4.y;
        As[acol + 2][arow] = a4.z; As[acol + 3][arow] = a4.w;
        Bs[acol + 0][arow] = b4.x; Bs[acol + 1][arow] = b4.y;
        Bs[acol + 2][arow] = b4.z; Bs[acol + 3][arow] = b4.w;
        __syncthreads();
#pragma unroll
        for (int k = 0; k < 8; k++) {
            float ar[8], br[8];
#pragma unroll
            for (int i = 0; i < 8; i++) ar[i] = As[k][ty * 8 + i];
#pragma unroll
            for (int j = 0; j < 8; j++) br[j] = Bs[k][tx * 8 + j];
#pragma unroll
            for (int i = 0; i < 8; i++)
#pragma unroll
                for (int j = 0; j < 8; j++)
                    acc[i][j] = fmaf(ar[i], br[j], acc[i][j]);
        }
        __syncthreads();
    }
    float xs[8], ys[8];
#pragma unroll
    for (int i = 0; i < 8; i++) xs[i] = x2[b * NTOK + i0 + ty * 8 + i];
#pragma unroll
    for (int j = 0; j < 8; j++) ys[j] = y2[b * NTOK + j0 + tx * 8 + j];
    float lmin = 3.4e38f, lmax = 0.f;
    float* Dp = g_D + (size_t)b * NTOK * NTOK;
#pragma unroll
    for (int i = 0; i < 8; i++) {
#pragma unroll
        for (int j = 0; j < 8; j++) {
            float d = sqrtf(fmaxf(xs[i] + ys[j] - 2.f * acc[i][j], 1e-12f));
            Dp[(size_t)(i0 + ty * 8 + i) * NTOK + (j0 + tx * 8 + j)] = d;
            lmin = fminf(lmin, d);
            lmax = fmaxf(lmax, d);
        }
    }
    // block-reduce min/max, one atomic pair per block
    __shared__ float smn[8], smx[8];
    int lane = tid & 31, w = tid >> 5;
#pragma unroll
    for (int o = 16; o > 0; o >>= 1) {
        lmin = fminf(lmin, __shfl_down_sync(0xffffffffu, lmin, o));
        lmax = fmaxf(lmax, __shfl_down_sync(0xffffffffu, lmax, o));
    }
    if (lane == 0) { smn[w] = lmin; smx[w] = lmax; }
    __syncthreads();
    if (tid == 0) {
        float mn = smn[0], mx = smx[0];
#pragma unroll
        for (int i = 1; i < 8; i++) { mn = fminf(mn, smn[i]); mx = fmaxf(mx, smx[i]); }
        atomicMin((unsigned int*)&stats[0], __float_as_uint(mn));
        atomicMax((unsigned int*)&stats[1], __float_as_uint(mx));
    }
}

// ---------------- distance-matrix reductions ----------------
// invr[b*N+i] = 1 / max(||D[b,i,:] - t||_2, 1e-12)
__global__ void row_invnorm_kernel(const float* __restrict__ stats, int which,
                                   float* __restrict__ invr) {
    int row = blockIdx.x;                      // b*NTOK + i
    float t = stats[which];
    const float* p = g_D + (size_t)row * NTOK;
    float acc = 0.f;
    for (int j = threadIdx.x; j < NTOK; j += 256) { float v = p[j] - t; acc += v * v; }
    float2 r = blockReduce2(acc, 0.f);
    if (threadIdx.x == 0) invr[row] = 1.f / fmaxf(sqrtf(r.x), 1e-12f);
}

// out[b*N+j] = 1 / max(||D[b,:,j] - t||_2, 1e-12)
__global__ void col_invnorm_kernel(const float* __restrict__ stats, int which,
                                   float* __restrict__ out) {
    int b = blockIdx.y;
    int j = blockIdx.x * 256 + threadIdx.x;
    float t = stats[which];
    const float* p = g_D + (size_t)b * NTOK * NTOK + j;
    float acc = 0.f;
    for (int i = 0; i < NTOK; i++) { float v = p[(size_t)i * NTOK] - t; acc += v * v; }
    out[b * NTOK + j] = 1.f / fmaxf(sqrtf(acc), 1e-12f);
}

// out[b*N+j] = sgn * sum_i (D[b,i,j] - t) * w[b*N+i]
__global__ void col_wsum_kernel(const float* __restrict__ stats, int which, float sgn,
                                const float* __restrict__ w, float* __restrict__ out) {
    int b = blockIdx.y;
    int j = blockIdx.x * 256 + threadIdx.x;
    float t = stats[which];
    const float* p = g_D + (size_t)b * NTOK * NTOK + j;
    const float* wb = w + b * NTOK;
    float acc = 0.f;
    for (int i = 0; i < NTOK; i++) acc += (p[(size_t)i * NTOK] - t) * wb[i];
    out[b * NTOK + j] = sgn * acc;
}

// out[b*N+j] = sgn * sum_i (D[b,j,i] - t) * w[b*N+i]
__global__ void row_wsum_kernel(const float* __restrict__ stats, int which, float sgn,
                                const float* __restrict__ w, float* __restrict__ out) {
    int row = blockIdx.x;                      // b*NTOK + j
    int b = row >> 10;
    float t = stats[which];
    const float* p = g_D + (size_t)row * NTOK;
    const float* wb = w + b * NTOK;
    float acc = 0.f;
    for (int i = threadIdx.x; i < NTOK; i += 256) acc += (p[i] - t) * wb[i];
    float2 r = blockReduce2(acc, 0.f);
    if (threadIdx.x == 0) out[row] = sgn * r.x;
}

// map1 = S_a + k*(al*(d11a+d12a)/2 + (1-al)*(d21a+d22a)/2); map2 analogous w/ positive set
__global__ void combine_maps_kernel(const float* __restrict__ theta, const float* __restrict__ alpha,
                                    float* __restrict__ map1, float* __restrict__ map2) {
    int i = blockIdx.x * 256 + threadIdx.x;
    float kk = tanhf(theta[0]) + 1.f;
    float al = 1.f / (1.f + expf(-alpha[0]));
    float m1 = g_vec[i] + kk * (al * 0.5f * (g_vec[2 * RPT + i] + g_vec[3 * RPT + i]) +
                                (1.f - al) * 0.5f * (g_vec[4 * RPT + i] + g_vec[5 * RPT + i]));
    float m2 = g_vec[RPT + i] + kk * (al * 0.5f * (g_vec[6 * RPT + i] + g_vec[7 * RPT + i]) +
                                      (1.f - al) * 0.5f * (g_vec[8 * RPT + i] + g_vec[9 * RPT + i]));
    map1[i] = m1;
    map2[i] = m2;
}

// xo = map*v + ln  (anchor/positive)  |  xo = map*v*ln  (negatives)
__global__ void combine_xo_kernel() {
    int row = blockIdx.x;
    float m = g_maps[row];                           // maps stored in tensor order
    const float* v = g_proj + (size_t)row * CH2 + CH;
    const float* l = g_ln + (size_t)row * CH;
    float* o = g_xo + (size_t)row * CH;
    bool addmode = row < 2 * RPT;
#pragma unroll
    for (int e = 0; e < 3; e++) {
        int c = threadIdx.x + e * 256;
        float val = m * v[c];
        o[c] = addmode ? (val + l[c]) : (val * l[c]);
    }
}

// ---------------- host ----------------
extern "C" void kernel_launch(void* const* d_in, const int* in_sizes, int n_in,
                              void* d_out, int out_size) {
    const float* anchor   = (const float*)d_in[0];
    const float* positive = (const float*)d_in[1];
    const float* neg1     = (const float*)d_in[2];
    const float* neg2     = (const float*)d_in[3];
    const float* n1w      = (const float*)d_in[4];
    const float* n1b      = (const float*)d_in[5];
    const float* n2w      = (const float*)d_in[6];
    const float* n2b      = (const float*)d_in[7];
    const float* projW    = (const float*)d_in[8];
    const float* projb    = (const float*)d_in[9];
    const float* fc1W     = (const float*)d_in[10];
    const float* fc1b     = (const float*)d_in[11];
    const float* fc2W     = (const float*)d_in[12];
    const float* fc2b     = (const float*)d_in[13];
    const float* theta    = (const float*)d_in[14];
    const float* alpha    = (const float*)d_in[15];
    float* out = (float*)d_out;

    float *ln, *proj, *xo, *h, *qk2, *stats, *vec, *scr, *maps;
    cudaGetSymbolAddress((void**)&ln,    g_ln);
    cudaGetSymbolAddress((void**)&proj,  g_proj);
    cudaGetSymbolAddress((void**)&xo,    g_xo);
    cudaGetSymbolAddress((void**)&h,     g_h);
    cudaGetSymbolAddress((void**)&qk2,   g_qk2);
    cudaGetSymbolAddress((void**)&stats, g_stats);
    cudaGetSymbolAddress((void**)&vec,   g_vec);
    cudaGetSymbolAddress((void**)&scr,   g_scr);
    cudaGetSymbolAddress((void**)&maps,  g_maps);

    init_stats_kernel<<<1, 32>>>();
    ln_gather_kernel<<<ROWS, 256>>>(anchor, positive, neg1, neg2, n1w, n1b);
    gemm_nn_kernel<<<dim3(CH2 / 128, ROWS / 128), 256>>>(ln, CH, projW, CH2, proj, CH2, CH,
                                                         projb, 0, nullptr, 0);
    qksq_kernel<<<ROWS, 256>>>();

    // attn calls: {anchor_t, positive_t, neg list (d11,d12,d21,d22 sources)}
    const int calls[3][6] = { {0, 1, 2, 3, 4, 5},
                              {2, 3, 0, 1, 4, 5},
                              {4, 5, 0, 1, 2, 3} };
    int slot = 0;
    for (int c = 0; c < 3; c++) {
        int ta = calls[c][0], tp = calls[c][1];
        const float* qa = proj + (size_t)ta * RPT * CH2;
        const float* qp = proj + (size_t)tp * RPT * CH2;

        // S_p = cdist(positive, anchor); min cancels -> use (max - D)
        cdist_kernel<<<dim3(8, 8, NB), 256>>>(qp, qk2 + tp * RPT, qa, qk2 + ta * RPT,
                                              stats + 2 * slot);
        row_invnorm_kernel<<<RPT, 256>>>(stats + 2 * slot, 1, scr);                 // invr
        col_invnorm_kernel<<<dim3(4, NB), 256>>>(stats + 2 * slot, 1, scr + RPT);   // invc
        col_wsum_kernel<<<dim3(4, NB), 256>>>(stats + 2 * slot, 1, -1.f, scr, vec);        // S_a
        row_wsum_kernel<<<RPT, 256>>>(stats + 2 * slot, 1, -1.f, scr + RPT, vec + RPT);    // S_p1
        slot++;

        // 8 proc(D) paths: negs vs anchor (q=0..3), negs vs positive (q=4..7)
        for (int q = 0; q < 8; q++) {
            int tn = calls[c][2 + (q & 3)];
            int tt = (q < 4) ? ta : tp;
            cdist_kernel<<<dim3(8, 8, NB), 256>>>(proj + (size_t)tn * RPT * CH2, qk2 + tn * RPT,
                                                  proj + (size_t)tt * RPT * CH2, qk2 + tt * RPT,
                                                  stats + 2 * slot);
            row_invnorm_kernel<<<RPT, 256>>>(stats + 2 * slot, 0, scr);
            col_wsum_kernel<<<dim3(4, NB), 256>>>(stats + 2 * slot, 0, 1.f, scr,
                                                  vec + (size_t)(2 + q) * RPT);
            slot++;
        }
        combine_maps_kernel<<<RPT / 256, 256>>>(theta, alpha,
                                                maps + (size_t)(2 * c) * RPT,
                                                maps + (size_t)(2 * c + 1) * RPT);
    }

    combine_xo_kernel<<<ROWS, 256>>>();
    ln_plain_kernel<<<ROWS, 256>>>(xo, n2w, n2b);
    gemm_nn_kernel<<<dim3(CH4 / 128, ROWS / 128), 256>>>(ln, CH, fc1W, CH4, h, CH4, CH,
                                                         fc1b, 1, nullptr, 0);
    gemm_nn_kernel<<<dim3(CH / 128, ROWS / 128), 256>>>(h, CH4, fc2W, CH, out, CH, CH4,
                                                        fc2b, 2, xo, CH);
}

// round 16
// speedup vs baseline: 3.3022x; 3.3022x over previous
#include <cuda_runtime.h>
#include <cuda_bf16.h>
#include <math.h>
#include <stdint.h>

#define NB 8
#define NTOK 1024
#define CH 768
#define CH2 1536
#define CH4 3072
#define RPT 8192
#define ROWS 49152

// ---------------- scratch ----------------
__device__ float g_ln[(size_t)ROWS * CH];
__device__ float g_proj[(size_t)ROWS * CH2];
__device__ float g_xo[(size_t)ROWS * CH];
__device__ float g_D[(size_t)NB * NTOK * NTOK];
__device__ float g_qk2[ROWS];
__device__ float g_stats[54];
__device__ float g_vec[10 * RPT];
__device__ float g_scr[2 * RPT];
__device__ float g_maps[6 * RPT];
__device__ __nv_bfloat16 g_lnh[(size_t)ROWS * CH];
__device__ __nv_bfloat16 g_lnl[(size_t)ROWS * CH];
__device__ __nv_bfloat16 g_qkh[(size_t)ROWS * CH];
__device__ __nv_bfloat16 g_hh[(size_t)ROWS * CH4];
__device__ __nv_bfloat16 g_hl[(size_t)ROWS * CH4];
#define WT_PROJ 0
#define WT_FC1  (1536 * 768)
#define WT_FC2  (1536 * 768 + 3072 * 768)
#define WT_TOT  (1536 * 768 + 3072 * 768 + 768 * 3072)
__device__ __nv_bfloat16 g_wth[WT_TOT];
__device__ __nv_bfloat16 g_wtl[WT_TOT];

// ---------------- PTX helpers (compute_80-safe only) ----------------
__device__ __forceinline__ uint32_t smem_u32(const void* p) {
    uint32_t a;
    asm("{ .reg .u64 t; cvta.to.shared.u64 t, %1; cvt.u32.u64 %0, t; }" : "=r"(a) : "l"(p));
    return a;
}
#define SWZ(x) ((x) ^ (((x) >> 3) & 0x70))
#define CP16(dst, src) \
    asm volatile("cp.async.cg.shared.global [%0], [%1], 16;" :: "r"(dst), "l"(src) : "memory")
#define CP_COMMIT() asm volatile("cp.async.commit_group;" ::: "memory")
#define CP_WAIT1()  asm volatile("cp.async.wait_group 1;" ::: "memory")
#define CP_WAIT0()  asm volatile("cp.async.wait_group 0;" ::: "memory")
#define LDSM4(r0, r1, r2, r3, addr) \
    asm volatile("ldmatrix.sync.aligned.m8n8.x4.shared.b16 {%0,%1,%2,%3}, [%4];" \
                 : "=r"(r0), "=r"(r1), "=r"(r2), "=r"(r3) : "r"(addr))
#define LDSM2(r0, r1, addr) \
    asm volatile("ldmatrix.sync.aligned.m8n8.x2.shared.b16 {%0,%1}, [%2];" \
                 : "=r"(r0), "=r"(r1) : "r"(addr))
#define MMA16816(d0, d1, d2, d3, a0, a1, a2, a3, b0, b1) \
    asm volatile("mma.sync.aligned.m16n8k16.row.col.f32.bf16.bf16.f32 " \
                 "{%0,%1,%2,%3}, {%4,%5,%6,%7}, {%8,%9}, {%0,%1,%2,%3};" \
                 : "+f"(d0), "+f"(d1), "+f"(d2), "+f"(d3) \
                 : "r"(a0), "r"(a1), "r"(a2), "r"(a3), "r"(b0), "r"(b1))

// load one [128][64]bf16 tile (16KB) into swizzled smem; 4x 16B per thread
__device__ __forceinline__ void load_tile(uint32_t dst, const __nv_bfloat16* __restrict__ src,
                                          int K, int k0) {
    const int tid = threadIdx.x;
#pragma unroll
    for (int i = 0; i < 4; i++) {
        int u = i * 256 + tid;
        int row = u >> 3, seg = u & 7;
        uint32_t off = SWZ((uint32_t)((row << 7) | (seg << 4)));
        CP16(dst + off, src + (size_t)row * K + k0 + seg * 8);
    }
}

__device__ __forceinline__ float gelu_exact(float x) {
    return 0.5f * x * (1.0f + erff(x * 0.70710678118654752f));
}

// ---------------- mma GEMM: C[r, f] = sum_k X[r,k]*WT[f,k]  (split-bf16, 3 passes) ----
// A = X rows (m), B = WT rows (n). block 128x128x64, 8 warps (2m x 4n), warp 64x32.
// MODE 0: proj (+bias -> fp32 g_proj stride CH2, bf16 qkh stride CH for f<CH)
// MODE 1: fc1  (+bias, gelu -> split bf16 stride CH4)
// MODE 2: fc2  (+bias + resid -> fp32 out stride CH)
template <int MODE>
__global__ void __launch_bounds__(256, 1)
mm_gemm_kernel(const __nv_bfloat16* __restrict__ Xh, const __nv_bfloat16* __restrict__ Xl,
               const __nv_bfloat16* __restrict__ Wh, const __nv_bfloat16* __restrict__ Wl,
               int K, const float* __restrict__ bias,
               float* __restrict__ outf, __nv_bfloat16* __restrict__ outh,
               __nv_bfloat16* __restrict__ outl, const float* __restrict__ resid) {
    extern __shared__ char smem[];
    const uint32_t sb = smem_u32(smem);
    const int tid = threadIdx.x;
    const size_t r0 = (size_t)blockIdx.y * 128;
    const int f0 = blockIdx.x * 128;
    const __nv_bfloat16* Ah = Xh + r0 * K;
    const __nv_bfloat16* Al = Xl + r0 * K;
    const __nv_bfloat16* Bh = Wh + (size_t)f0 * K;
    const __nv_bfloat16* Bl = Wl + (size_t)f0 * K;
    const int warp = tid >> 5, lane = tid & 31;
    const int wm = warp & 1, wn = warp >> 1;

    float acc[4][4][4] = {};

    const int nch = K / 64;
    load_tile(sb + 0,     Ah, K, 0);
    load_tile(sb + 16384, Al, K, 0);
    load_tile(sb + 32768, Bh, K, 0);
    load_tile(sb + 49152, Bl, K, 0);
    CP_COMMIT();
    for (int c = 0; c < nch; c++) {
        const uint32_t st = sb + (uint32_t)(c & 1) * 65536u;
        if (c + 1 < nch) {
            uint32_t sn = sb + (uint32_t)((c + 1) & 1) * 65536u;
            load_tile(sn + 0,     Ah, K, (c + 1) * 64);
            load_tile(sn + 16384, Al, K, (c + 1) * 64);
            load_tile(sn + 32768, Bh, K, (c + 1) * 64);
            load_tile(sn + 49152, Bl, K, (c + 1) * 64);
            CP_COMMIT();
            CP_WAIT1();
        } else {
            CP_WAIT0();
        }
        __syncthreads();
#pragma unroll
        for (int pass = 0; pass < 3; pass++) {
            const uint32_t abase = st + ((pass == 2) ? 16384u : 0u);
            const uint32_t bbase = st + ((pass == 1) ? 49152u : 32768u);
#pragma unroll
            for (int ks = 0; ks < 4; ks++) {
                uint32_t a[4][4], b[4][2];
#pragma unroll
                for (int am = 0; am < 4; am++) {
                    int row = wm * 64 + am * 16 + (lane & 15);
                    int kb = ks * 32 + ((lane >> 4) << 4);
                    LDSM4(a[am][0], a[am][1], a[am][2], a[am][3],
                          abase + SWZ((uint32_t)(row * 128 + kb)));
                }
#pragma unroll
                for (int bn = 0; bn < 4; bn++) {
                    int row = wn * 32 + bn * 8 + (lane & 7);
                    int kb = ks * 32 + (((lane >> 3) & 1) << 4);
                    LDSM2(b[bn][0], b[bn][1],
                          bbase + SWZ((uint32_t)(row * 128 + kb)));
                }
#pragma unroll
                for (int am = 0; am < 4; am++)
#pragma unroll
                    for (int bn = 0; bn < 4; bn++)
                        MMA16816(acc[am][bn][0], acc[am][bn][1], acc[am][bn][2], acc[am][bn][3],
                                 a[am][0], a[am][1], a[am][2], a[am][3], b[bn][0], b[bn][1]);
            }
        }
        __syncthreads();
    }
    // epilogue: c0,c1 -> (row=lane/4, col=2*(lane%4)+{0,1}); c2,c3 -> row+8
    const bool isqk = (MODE == 0) && (f0 < CH);
#pragma unroll
    for (int am = 0; am < 4; am++) {
#pragma unroll
        for (int half = 0; half < 2; half++) {
            size_t r = r0 + wm * 64 + am * 16 + (lane >> 2) + half * 8;
#pragma unroll
            for (int bn = 0; bn < 4; bn++) {
                int f = f0 + wn * 32 + bn * 8 + 2 * (lane & 3);
                float2 bv = *(const float2*)&bias[f];
                float v0 = acc[am][bn][2 * half + 0] + bv.x;
                float v1 = acc[am][bn][2 * half + 1] + bv.y;
                if (MODE == 0) {
                    float2 o = {v0, v1};
                    *(float2*)&outf[r * CH2 + f] = o;
                    if (isqk) {
                        __nv_bfloat162 h2;
                        h2.x = __float2bfloat16(v0);
                        h2.y = __float2bfloat16(v1);
                        *(__nv_bfloat162*)&outh[r * CH + f] = h2;
                    }
                } else if (MODE == 1) {
                    float g0 = gelu_exact(v0), g1 = gelu_exact(v1);
                    __nv_bfloat162 h2, l2;
                    h2.x = __float2bfloat16(g0);
                    h2.y = __float2bfloat16(g1);
                    l2.x = __float2bfloat16(g0 - __bfloat162float(h2.x));
                    l2.y = __float2bfloat16(g1 - __bfloat162float(h2.y));
                    *(__nv_bfloat162*)&outh[r * CH4 + f] = h2;
                    *(__nv_bfloat162*)&outl[r * CH4 + f] = l2;
                } else {
                    float2 rs = *(const float2*)&resid[r * CH + f];
                    float2 o = {v0 + rs.x, v1 + rs.y};
                    *(float2*)&outf[r * CH + f] = o;
                }
            }
        }
    }
}

// ---------------- mma cdist: D[b,i,j] = ||X_i - Y_j||, fused global min/max ----------
// A = X rows (m=i), B = Y rows (n=j). block 128x128, K=CH. single bf16 pass.
__global__ void __launch_bounds__(256, 1)
mm_cdist_kernel(const __nv_bfloat16* __restrict__ Xq, const float* __restrict__ x2,
                const __nv_bfloat16* __restrict__ Yq, const float* __restrict__ y2,
                float* __restrict__ stats) {
    extern __shared__ char smem[];
    const uint32_t sb = smem_u32(smem);
    const int tid = threadIdx.x;
    const int b = blockIdx.z;
    const int i0 = blockIdx.y * 128;
    const int j0 = blockIdx.x * 128;
    const __nv_bfloat16* At = Xq + (size_t)(b * NTOK + i0) * CH;
    const __nv_bfloat16* Bt = Yq + (size_t)(b * NTOK + j0) * CH;
    const int warp = tid >> 5, lane = tid & 31;
    const int wm = warp & 1, wn = warp >> 1;

    float acc[4][4][4] = {};

    const int nch = CH / 64;  // 12
    load_tile(sb + 0,     At, CH, 0);
    load_tile(sb + 16384, Bt, CH, 0);
    CP_COMMIT();
    for (int c = 0; c < nch; c++) {
        const uint32_t st = sb + (uint32_t)(c & 1) * 32768u;
        if (c + 1 < nch) {
            uint32_t sn = sb + (uint32_t)((c + 1) & 1) * 32768u;
            load_tile(sn + 0,     At, CH, (c + 1) * 64);
            load_tile(sn + 16384, Bt, CH, (c + 1) * 64);
            CP_COMMIT();
            CP_WAIT1();
        } else {
            CP_WAIT0();
        }
        __syncthreads();
#pragma unroll
        for (int ks = 0; ks < 4; ks++) {
            uint32_t a[4][4], bb[4][2];
#pragma unroll
            for (int am = 0; am < 4; am++) {
                int row = wm * 64 + am * 16 + (lane & 15);
                int kb = ks * 32 + ((lane >> 4) << 4);
                LDSM4(a[am][0], a[am][1], a[am][2], a[am][3],
                      st + SWZ((uint32_t)(row * 128 + kb)));
            }
#pragma unroll
            for (int bn = 0; bn < 4; bn++) {
                int row = wn * 32 + bn * 8 + (lane & 7);
                int kb = ks * 32 + (((lane >> 3) & 1) << 4);
                LDSM2(bb[bn][0], bb[bn][1],
                      st + 16384u + SWZ((uint32_t)(row * 128 + kb)));
            }
#pragma unroll
            for (int am = 0; am < 4; am++)
#pragma unroll
                for (int bn = 0; bn < 4; bn++)
                    MMA16816(acc[am][bn][0], acc[am][bn][1], acc[am][bn][2], acc[am][bn][3],
                             a[am][0], a[am][1], a[am][2], a[am][3], bb[bn][0], bb[bn][1]);
        }
        __syncthreads();
    }
    // epilogue
    const float* x2b = x2 + b * NTOK;
    const float* y2b = y2 + b * NTOK;
    float* Dp = g_D + (size_t)b * NTOK * NTOK;
    float lmin = 3.4e38f, lmax = 0.f;
#pragma unroll
    for (int am = 0; am < 4; am++) {
#pragma unroll
        for (int half = 0; half < 2; half++) {
            int i = i0 + wm * 64 + am * 16 + (lane >> 2) + half * 8;
            float xi = x2b[i];
#pragma unroll
            for (int bn = 0; bn < 4; bn++) {
                int j = j0 + wn * 32 + bn * 8 + 2 * (lane & 3);
                float2 yj = *(const float2*)&y2b[j];
                float d0 = sqrtf(fmaxf(xi + yj.x - 2.f * acc[am][bn][2 * half + 0], 1e-12f));
                float d1 = sqrtf(fmaxf(xi + yj.y - 2.f * acc[am][bn][2 * half + 1], 1e-12f));
                float2 o = {d0, d1};
                *(float2*)&Dp[(size_t)i * NTOK + j] = o;
                lmin = fminf(lmin, fminf(d0, d1));
                lmax = fmaxf(lmax, fmaxf(d0, d1));
            }
        }
    }
    __shared__ float smn[8], smx[8];
#pragma unroll
    for (int o = 16; o > 0; o >>= 1) {
        lmin = fminf(lmin, __shfl_down_sync(0xffffffffu, lmin, o));
        lmax = fmaxf(lmax, __shfl_down_sync(0xffffffffu, lmax, o));
    }
    if (lane == 0) { smn[warp] = lmin; smx[warp] = lmax; }
    __syncthreads();
    if (tid == 0) {
        float mn = smn[0], mx = smx[0];
#pragma unroll
        for (int k = 1; k < 8; k++) { mn = fminf(mn, smn[k]); mx = fmaxf(mx, smx[k]); }
        atomicMin((unsigned int*)&stats[0], __float_as_uint(mn));
        atomicMax((unsigned int*)&stats[1], __float_as_uint(mx));
    }
}

// ---------------- weight transpose + bf16 split: W[K,N] -> WT[N,K] hi/lo ----------------
__global__ void wt_split_kernel(const float* __restrict__ W, int K, int N,
                                __nv_bfloat16* __restrict__ Th, __nv_bfloat16* __restrict__ Tl) {
    __shared__ float t[32][33];
    int k = blockIdx.y * 32 + threadIdx.y;
    int n = blockIdx.x * 32 + threadIdx.x;
    t[threadIdx.y][threadIdx.x] = W[(size_t)k * N + n];
    __syncthreads();
    int nn = blockIdx.x * 32 + threadIdx.y;
    int kk = blockIdx.y * 32 + threadIdx.x;
    float v = t[threadIdx.x][threadIdx.y];
    __nv_bfloat16 h = __float2bfloat16(v);
    Th[(size_t)nn * K + kk] = h;
    Tl[(size_t)nn * K + kk] = __float2bfloat16(v - __bfloat162float(h));
}

// ---------------- elementwise / reductions ----------------
__device__ __forceinline__ float2 blockReduce2(float a, float b) {
    __shared__ float sa[8], sb2[8];
    __shared__ float2 res;
    int lane = threadIdx.x & 31, w = threadIdx.x >> 5;
#pragma unroll
    for (int o = 16; o > 0; o >>= 1) {
        a += __shfl_down_sync(0xffffffffu, a, o);
        b += __shfl_down_sync(0xffffffffu, b, o);
    }
    if (lane == 0) { sa[w] = a; sb2[w] = b; }
    __syncthreads();
    if (threadIdx.x == 0) {
        float ta = 0.f, tb = 0.f;
#pragma unroll
        for (int i = 0; i < 8; i++) { ta += sa[i]; tb += sb2[i]; }
        res.x = ta; res.y = tb;
    }
    __syncthreads();
    return res;
}

__global__ void init_stats_kernel() {
    int i = threadIdx.x;
    if (i < 27) {
        g_stats[2 * i] = __int_as_float(0x7f800000);
        g_stats[2 * i + 1] = 0.f;
    }
}

__device__ __forceinline__ void ln_body(const float* __restrict__ src,
                                        const float* __restrict__ w,
                                        const float* __restrict__ bb,
                                        float* __restrict__ dst,
                                        __nv_bfloat16* __restrict__ dh,
                                        __nv_bfloat16* __restrict__ dl) {
    int c = threadIdx.x;
    float v0 = src[c], v1 = src[c + 256], v2 = src[c + 512];
    float2 r = blockReduce2(v0 + v1 + v2, v0 * v0 + v1 * v1 + v2 * v2);
    float mu = r.x * (1.0f / CH);
    float var = r.y * (1.0f / CH) - mu * mu;
    float inv = rsqrtf(var + 1e-5f);
#pragma unroll
    for (int e = 0; e < 3; e++) {
        int cc = c + e * 256;
        float v = (e == 0) ? v0 : (e == 1) ? v1 : v2;
        float o = (v - mu) * inv * w[cc] + bb[cc];
        dst[cc] = o;
        __nv_bfloat16 h = __float2bfloat16(o);
        dh[cc] = h;
        dl[cc] = __float2bfloat16(o - __bfloat162float(h));
    }
}

__global__ void ln_gather_kernel(const float* __restrict__ anc, const float* __restrict__ pos,
                                 const float* __restrict__ n1, const float* __restrict__ n2,
                                 const float* __restrict__ w, const float* __restrict__ bb) {
    int row = blockIdx.x;
    int t = row / RPT, q = row - t * RPT;
    const float* src;
    switch (t) {
        case 0: src = anc + (size_t)q * CH; break;
        case 1: src = pos + (size_t)q * CH; break;
        case 2: src = n1 + (size_t)q * CH; break;
        case 3: src = n1 + ((size_t)RPT + q) * CH; break;
        case 4: src = n2 + (size_t)q * CH; break;
        default: src = n2 + ((size_t)RPT + q) * CH; break;
    }
    ln_body(src, w, bb, g_ln + (size_t)row * CH, g_lnh + (size_t)row * CH, g_lnl + (size_t)row * CH);
}

__global__ void ln_plain_kernel(const float* __restrict__ x,
                                const float* __restrict__ w, const float* __restrict__ bb) {
    int row = blockIdx.x;
    ln_body(x + (size_t)row * CH, w, bb, g_ln + (size_t)row * CH,
            g_lnh + (size_t)row * CH, g_lnl + (size_t)row * CH);
}

__global__ void qksq_kernel() {
    int row = blockIdx.x;
    const float* p = g_proj + (size_t)row * CH2;
    int c = threadIdx.x;
    float v0 = p[c], v1 = p[c + 256], v2 = p[c + 512];
    float2 r = blockReduce2(v0 * v0 + v1 * v1 + v2 * v2, 0.f);
    if (threadIdx.x == 0) g_qk2[row] = r.x;
}

__global__ void row_invnorm_kernel(const float* __restrict__ stats, int which,
                                   float* __restrict__ invr) {
    int row = blockIdx.x;
    float t = stats[which];
    const float* p = g_D + (size_t)row * NTOK;
    float acc = 0.f;
    for (int j = threadIdx.x; j < NTOK; j += 256) { float v = p[j] - t; acc += v * v; }
    float2 r = blockReduce2(acc, 0.f);
    if (threadIdx.x == 0) invr[row] = 1.f / fmaxf(sqrtf(r.x), 1e-12f);
}

__global__ void col_invnorm_kernel(const float* __restrict__ stats, int which,
                                   float* __restrict__ out) {
    int b = blockIdx.y;
    int j = blockIdx.x * 256 + threadIdx.x;
    float t = stats[which];
    const float* p = g_D + (size_t)b * NTOK * NTOK + j;
    float acc = 0.f;
    for (int i = 0; i < NTOK; i++) { float v = p[(size_t)i * NTOK] - t; acc += v * v; }
    out[b * NTOK + j] = 1.f / fmaxf(sqrtf(acc), 1e-12f);
}

__global__ void col_wsum_kernel(const float* __restrict__ stats, int which, float sgn,
                                const float* __restrict__ w, float* __restrict__ out) {
    int b = blockIdx.y;
    int j = blockIdx.x * 256 + threadIdx.x;
    float t = stats[which];
    const float* p = g_D + (size_t)b * NTOK * NTOK + j;
    const float* wb = w + b * NTOK;
    float acc = 0.f;
    for (int i = 0; i < NTOK; i++) acc += (p[(size_t)i * NTOK] - t) * wb[i];
    out[b * NTOK + j] = sgn * acc;
}

__global__ void row_wsum_kernel(const float* __restrict__ stats, int which, float sgn,
                                const float* __restrict__ w, float* __restrict__ out) {
    int row = blockIdx.x;
    int b = row >> 10;
    float t = stats[which];
    const float* p = g_D + (size_t)row * NTOK;
    const float* wb = w + b * NTOK;
    float acc = 0.f;
    for (int i = threadIdx.x; i < NTOK; i += 256) acc += (p[i] - t) * wb[i];
    float2 r = blockReduce2(acc, 0.f);
    if (threadIdx.x == 0) out[row] = sgn * r.x;
}

__global__ void combine_maps_kernel(const float* __restrict__ theta, const float* __restrict__ alpha,
                                    float* __restrict__ map1, float* __restrict__ map2) {
    int i = blockIdx.x * 256 + threadIdx.x;
    float kk = tanhf(theta[0]) + 1.f;
    float al = 1.f / (1.f + expf(-alpha[0]));
    map1[i] = g_vec[i] + kk * (al * 0.5f * (g_vec[2 * RPT + i] + g_vec[3 * RPT + i]) +
                               (1.f - al) * 0.5f * (g_vec[4 * RPT + i] + g_vec[5 * RPT + i]));
    map2[i] = g_vec[RPT + i] + kk * (al * 0.5f * (g_vec[6 * RPT + i] + g_vec[7 * RPT + i]) +
                                     (1.f - al) * 0.5f * (g_vec[8 * RPT + i] + g_vec[9 * RPT + i]));
}

__global__ void combine_xo_kernel() {
    int row = blockIdx.x;
    float m = g_maps[row];
    const float* v = g_proj + (size_t)row * CH2 + CH;
    const float* l = g_ln + (size_t)row * CH;
    float* o = g_xo + (size_t)row * CH;
    bool addmode = row < 2 * RPT;
#pragma unroll
    for (int e = 0; e < 3; e++) {
        int c = threadIdx.x + e * 256;
        float val = m * v[c];
        o[c] = addmode ? (val + l[c]) : (val * l[c]);
    }
}

// ---------------- host ----------------
extern "C" void kernel_launch(void* const* d_in, const int* in_sizes, int n_in,
                              void* d_out, int out_size) {
    const float* anchor   = (const float*)d_in[0];
    const float* positive = (const float*)d_in[1];
    const float* neg1     = (const float*)d_in[2];
    const float* neg2     = (const float*)d_in[3];
    const float* n1w      = (const float*)d_in[4];
    const float* n1b      = (const float*)d_in[5];
    const float* n2w      = (const float*)d_in[6];
    const float* n2b      = (const float*)d_in[7];
    const float* projW    = (const float*)d_in[8];
    const float* projb    = (const float*)d_in[9];
    const float* fc1W     = (const float*)d_in[10];
    const float* fc1b     = (const float*)d_in[11];
    const float* fc2W     = (const float*)d_in[12];
    const float* fc2b     = (const float*)d_in[13];
    const float* theta    = (const float*)d_in[14];
    const float* alpha    = (const float*)d_in[15];
    float* out = (float*)d_out;

    float *proj, *xo, *qk2, *stats, *vec, *scr, *maps;
    __nv_bfloat16 *lnh, *lnl, *qkh, *hh, *hl, *wth, *wtl;
    cudaGetSymbolAddress((void**)&proj,  g_proj);
    cudaGetSymbolAddress((void**)&xo,    g_xo);
    cudaGetSymbolAddress((void**)&qk2,   g_qk2);
    cudaGetSymbolAddress((void**)&stats, g_stats);
    cudaGetSymbolAddress((void**)&vec,   g_vec);
    cudaGetSymbolAddress((void**)&scr,   g_scr);
    cudaGetSymbolAddress((void**)&maps,  g_maps);
    cudaGetSymbolAddress((void**)&lnh,   g_lnh);
    cudaGetSymbolAddress((void**)&lnl,   g_lnl);
    cudaGetSymbolAddress((void**)&qkh,   g_qkh);
    cudaGetSymbolAddress((void**)&hh,    g_hh);
    cudaGetSymbolAddress((void**)&hl,    g_hl);
    cudaGetSymbolAddress((void**)&wth,   g_wth);
    cudaGetSymbolAddress((void**)&wtl,   g_wtl);

    const int GEMM_SMEM  = 131072;  // 2 stages x (Ah,Al,Bh,Bl 16KB each)
    const int CDIST_SMEM = 65536;   // 2 stages x (A,B 16KB each)
    cudaFuncSetAttribute(mm_gemm_kernel<0>, cudaFuncAttributeMaxDynamicSharedMemorySize, GEMM_SMEM);
    cudaFuncSetAttribute(mm_gemm_kernel<1>, cudaFuncAttributeMaxDynamicSharedMemorySize, GEMM_SMEM);
    cudaFuncSetAttribute(mm_gemm_kernel<2>, cudaFuncAttributeMaxDynamicSharedMemorySize, GEMM_SMEM);
    cudaFuncSetAttribute(mm_cdist_kernel,   cudaFuncAttributeMaxDynamicSharedMemorySize, CDIST_SMEM);

    init_stats_kernel<<<1, 32>>>();
    wt_split_kernel<<<dim3(1536 / 32, 768 / 32),  dim3(32, 32)>>>(projW, 768,  1536, wth + WT_PROJ, wtl + WT_PROJ);
    wt_split_kernel<<<dim3(3072 / 32, 768 / 32),  dim3(32, 32)>>>(fc1W,  768,  3072, wth + WT_FC1,  wtl + WT_FC1);
    wt_split_kernel<<<dim3(768 / 32,  3072 / 32), dim3(32, 32)>>>(fc2W,  3072, 768,  wth + WT_FC2,  wtl + WT_FC2);

    ln_gather_kernel<<<ROWS, 256>>>(anchor, positive, neg1, neg2, n1w, n1b);
    mm_gemm_kernel<0><<<dim3(CH2 / 128, ROWS / 128), 256, GEMM_SMEM>>>(
        lnh, lnl, wth + WT_PROJ, wtl + WT_PROJ, CH, projb, proj, qkh, nullptr, nullptr);
    qksq_kernel<<<ROWS, 256>>>();

    const int calls[3][6] = { {0, 1, 2, 3, 4, 5},
                              {2, 3, 0, 1, 4, 5},
                              {4, 5, 0, 1, 2, 3} };
    int slot = 0;
    for (int c = 0; c < 3; c++) {
        int ta = calls[c][0], tp = calls[c][1];
        // S_p = cdist(positive, anchor): rows i = positive, cols j = anchor
        mm_cdist_kernel<<<dim3(8, 8, NB), 256, CDIST_SMEM>>>(
            qkh + (size_t)tp * RPT * CH, qk2 + tp * RPT,
            qkh + (size_t)ta * RPT * CH, qk2 + ta * RPT, stats + 2 * slot);
        row_invnorm_kernel<<<RPT, 256>>>(stats + 2 * slot, 1, scr);
        col_invnorm_kernel<<<dim3(4, NB), 256>>>(stats + 2 * slot, 1, scr + RPT);
        col_wsum_kernel<<<dim3(4, NB), 256>>>(stats + 2 * slot, 1, -1.f, scr, vec);
        row_wsum_kernel<<<RPT, 256>>>(stats + 2 * slot, 1, -1.f, scr + RPT, vec + RPT);
        slot++;
        for (int q = 0; q < 8; q++) {
            int tn = calls[c][2 + (q & 3)];
            int tt = (q < 4) ? ta : tp;
            mm_cdist_kernel<<<dim3(8, 8, NB), 256, CDIST_SMEM>>>(
                qkh + (size_t)tn * RPT * CH, qk2 + tn * RPT,
                qkh + (size_t)tt * RPT * CH, qk2 + tt * RPT, stats + 2 * slot);
            row_invnorm_kernel<<<RPT, 256>>>(stats + 2 * slot, 0, scr);
            col_wsum_kernel<<<dim3(4, NB), 256>>>(stats + 2 * slot, 0, 1.f, scr,
                                                  vec + (size_t)(2 + q) * RPT);
            slot++;
        }
        combine_maps_kernel<<<RPT / 256, 256>>>(theta, alpha,
                                                maps + (size_t)(2 * c) * RPT,
                                                maps + (size_t)(2 * c + 1) * RPT);
    }

    combine_xo_kernel<<<ROWS, 256>>>();
    ln_plain_kernel<<<ROWS, 256>>>(xo, n2w, n2b);
    mm_gemm_kernel<1><<<dim3(CH4 / 128, ROWS / 128), 256, GEMM_SMEM>>>(
        lnh, lnl, wth + WT_FC1, wtl + WT_FC1, CH, fc1b, nullptr, hh, hl, nullptr);
    mm_gemm_kernel<2><<<dim3(CH / 128, ROWS / 128), 256, GEMM_SMEM>>>(
        hh, hl, wth + WT_FC2, wtl + WT_FC2, CH4, fc2b, out, nullptr, nullptr, xo);
}